// round 6
// baseline (speedup 1.0000x reference)
#include <cuda_runtime.h>
#include <cstdint>
#include <math.h>

typedef unsigned long long u64;

// Problem constants
#define Tt 512
#define Bb 256
#define Dd 256
#define Hh 1024
#define Rr 64

// Scan tiling
#define BT 16    // batch rows per cluster
#define HT 128   // hidden slice per CTA
#define NH 8     // cluster size

// Scratch
__device__ float g_xw1[(size_t)Tt * Bb * Rr];          // 33.5 MB
__device__ float g_wx2[(size_t)Tt * Bb * Hh];          // 537 MB

// ---------------- packed f32x2 helpers ----------------
__device__ __forceinline__ u64 fma2(u64 a, u64 b, u64 c) {
    u64 d;
    asm("fma.rn.f32x2 %0, %1, %2, %3;" : "=l"(d) : "l"(a), "l"(b), "l"(c));
    return d;
}
__device__ __forceinline__ u64 add2(u64 a, u64 b) {
    u64 d;
    asm("add.rn.f32x2 %0, %1, %2;" : "=l"(d) : "l"(a), "l"(b));
    return d;
}
__device__ __forceinline__ u64 dup2(float x) {
    u64 d;
    asm("mov.b64 %0, {%1, %1};" : "=l"(d) : "f"(x));
    return d;
}
__device__ __forceinline__ u64 pack2(float x, float y) {
    u64 d;
    asm("mov.b64 %0, {%1, %2};" : "=l"(d) : "f"(x), "f"(y));
    return d;
}
__device__ __forceinline__ void unpack2(u64 v, float& x, float& y) {
    asm("mov.b64 {%0, %1}, %2;" : "=f"(x), "=f"(y) : "l"(v));
}
__device__ __forceinline__ void cluster_sync_() {
    asm volatile("barrier.cluster.arrive.aligned;" ::: "memory");
    asm volatile("barrier.cluster.wait.aligned;" ::: "memory");
}
__device__ __forceinline__ uint32_t mapa_rank(uint32_t laddr, uint32_t rank) {
    uint32_t r;
    asm("mapa.shared::cluster.u32 %0, %1, %2;" : "=r"(r) : "r"(laddr), "r"(rank));
    return r;
}
__device__ __forceinline__ float2 ld_dsmem2(uint32_t addr) {
    float2 v;
    asm volatile("ld.shared::cluster.v2.f32 {%0, %1}, [%2];"
                 : "=f"(v.x), "=f"(v.y) : "r"(addr));
    return v;
}
__device__ __forceinline__ float4 ld_dsmem4(uint32_t addr) {
    float4 v;
    asm volatile("ld.shared::cluster.v4.f32 {%0, %1, %2, %3}, [%4];"
                 : "=f"(v.x), "=f"(v.y), "=f"(v.z), "=f"(v.w) : "r"(addr));
    return v;
}
__device__ __forceinline__ float sigmoidf_(float x) {
    return 1.0f / (1.0f + __expf(-x));
}

// ======================================================================
// Kernel 1: xw1[m][r] = sum_d x[m][d] * W1[r][d]
// ======================================================================
__global__ void __launch_bounds__(256) xw1_kernel(const float* __restrict__ x,
                                                  const float* __restrict__ W1)
{
    __shared__ float Ast[64 * 64];
    __shared__ float Bst[64 * 64];

    const int tid = threadIdx.x;
    const int m0  = blockIdx.x * 64;
    const int tx  = tid & 15;
    const int ty  = tid >> 4;

    float acc[4][4];
    #pragma unroll
    for (int i = 0; i < 4; i++)
        #pragma unroll
        for (int j = 0; j < 4; j++) acc[i][j] = 0.0f;

    for (int kk = 0; kk < Dd; kk += 64) {
        #pragma unroll
        for (int i = 0; i < 4; i++) {
            int s   = tid + i * 256;
            int row = s >> 4;
            int kq  = s & 15;
            float4 a = *(const float4*)(x  + (size_t)(m0 + row) * Dd + kk + kq * 4);
            Ast[(kq * 4 + 0) * 64 + row] = a.x;
            Ast[(kq * 4 + 1) * 64 + row] = a.y;
            Ast[(kq * 4 + 2) * 64 + row] = a.z;
            Ast[(kq * 4 + 3) * 64 + row] = a.w;
            float4 b = *(const float4*)(W1 + (size_t)row * Dd + kk + kq * 4);
            Bst[(kq * 4 + 0) * 64 + row] = b.x;
            Bst[(kq * 4 + 1) * 64 + row] = b.y;
            Bst[(kq * 4 + 2) * 64 + row] = b.z;
            Bst[(kq * 4 + 3) * 64 + row] = b.w;
        }
        __syncthreads();
        #pragma unroll
        for (int k = 0; k < 64; k++) {
            float4 a = *(const float4*)(Ast + k * 64 + ty * 4);
            float4 b = *(const float4*)(Bst + k * 64 + tx * 4);
            acc[0][0] = fmaf(a.x, b.x, acc[0][0]); acc[0][1] = fmaf(a.x, b.y, acc[0][1]);
            acc[0][2] = fmaf(a.x, b.z, acc[0][2]); acc[0][3] = fmaf(a.x, b.w, acc[0][3]);
            acc[1][0] = fmaf(a.y, b.x, acc[1][0]); acc[1][1] = fmaf(a.y, b.y, acc[1][1]);
            acc[1][2] = fmaf(a.y, b.z, acc[1][2]); acc[1][3] = fmaf(a.y, b.w, acc[1][3]);
            acc[2][0] = fmaf(a.z, b.x, acc[2][0]); acc[2][1] = fmaf(a.z, b.y, acc[2][1]);
            acc[2][2] = fmaf(a.z, b.z, acc[2][2]); acc[2][3] = fmaf(a.z, b.w, acc[2][3]);
            acc[3][0] = fmaf(a.w, b.x, acc[3][0]); acc[3][1] = fmaf(a.w, b.y, acc[3][1]);
            acc[3][2] = fmaf(a.w, b.z, acc[3][2]); acc[3][3] = fmaf(a.w, b.w, acc[3][3]);
        }
        __syncthreads();
    }

    #pragma unroll
    for (int i = 0; i < 4; i++) {
        float4 o = make_float4(acc[i][0], acc[i][1], acc[i][2], acc[i][3]);
        *(float4*)(g_xw1 + (size_t)(m0 + ty * 4 + i) * Rr + tx * 4) = o;
    }
}

// ======================================================================
// Kernel 2: wx2[m][h] = sum_r xw1[m][r] * W2[h][r]
// ======================================================================
#define PM 132
__global__ void __launch_bounds__(256) wx2_kernel(const float* __restrict__ W2)
{
    extern __shared__ float smg[];
    float* Ast = smg;
    float* Bst = smg + 64 * PM;

    const int tid = threadIdx.x;
    const int m0  = blockIdx.x * 128;
    const int h0  = blockIdx.y * 128;

    #pragma unroll
    for (int i = 0; i < 8; i++) {
        int s  = tid + i * 256;
        int mm = s >> 4;
        int rq = s & 15;
        float4 a = *(const float4*)(g_xw1 + (size_t)(m0 + mm) * 64 + rq * 4);
        Ast[(rq * 4 + 0) * PM + mm] = a.x;
        Ast[(rq * 4 + 1) * PM + mm] = a.y;
        Ast[(rq * 4 + 2) * PM + mm] = a.z;
        Ast[(rq * 4 + 3) * PM + mm] = a.w;
        float4 b = *(const float4*)(W2 + (size_t)(h0 + mm) * 64 + rq * 4);
        Bst[(rq * 4 + 0) * PM + mm] = b.x;
        Bst[(rq * 4 + 1) * PM + mm] = b.y;
        Bst[(rq * 4 + 2) * PM + mm] = b.z;
        Bst[(rq * 4 + 3) * PM + mm] = b.w;
    }
    __syncthreads();

    const int tx = tid & 15;
    const int ty = tid >> 4;

    u64 acc[4][8];
    #pragma unroll
    for (int i = 0; i < 4; i++)
        #pragma unroll
        for (int j = 0; j < 8; j++) acc[i][j] = 0ull;

    #pragma unroll 4
    for (int k = 0; k < 64; k++) {
        const u64* ap = (const u64*)(Ast + k * PM + ty * 8);
        u64 a0 = ap[0], a1 = ap[1], a2 = ap[2], a3 = ap[3];
        const float* bp = Bst + k * PM + tx * 8;
        float4 b0 = *(const float4*)(bp);
        float4 b1 = *(const float4*)(bp + 4);
        float bs[8] = {b0.x, b0.y, b0.z, b0.w, b1.x, b1.y, b1.z, b1.w};
        #pragma unroll
        for (int j = 0; j < 8; j++) {
            u64 bd = dup2(bs[j]);
            acc[0][j] = fma2(a0, bd, acc[0][j]);
            acc[1][j] = fma2(a1, bd, acc[1][j]);
            acc[2][j] = fma2(a2, bd, acc[2][j]);
            acc[3][j] = fma2(a3, bd, acc[3][j]);
        }
    }

    #pragma unroll
    for (int i = 0; i < 4; i++) {
        float lo[8], hi[8];
        #pragma unroll
        for (int j = 0; j < 8; j++) unpack2(acc[i][j], lo[j], hi[j]);
        size_t base0 = (size_t)(m0 + ty * 8 + 2 * i)     * Hh + h0 + tx * 8;
        size_t base1 = (size_t)(m0 + ty * 8 + 2 * i + 1) * Hh + h0 + tx * 8;
        *(float4*)(g_wx2 + base0)     = make_float4(lo[0], lo[1], lo[2], lo[3]);
        *(float4*)(g_wx2 + base0 + 4) = make_float4(lo[4], lo[5], lo[6], lo[7]);
        *(float4*)(g_wx2 + base1)     = make_float4(hi[0], hi[1], hi[2], hi[3]);
        *(float4*)(g_wx2 + base1 + 4) = make_float4(hi[4], hi[5], hi[6], hi[7]);
    }
}

// ======================================================================
// Kernel 3: persistent cluster scan. 16 clusters x 8 CTAs = 128 CTAs,
// 1 CTA/SM (occ 1). BT=16 batch rows per cluster (8 f32x2 pairs).
// Weights live in registers: phase A thread holds 32 U1 floats,
// phase B thread holds its 64-float U2 column.
// p exchange: local reduce -> csync -> DSMEM reduce-scatter (each rank
// sums its 64-slot chunk over 8 ranks) -> csync -> DSMEM all-gather.
// slot = bp*64 + r  (bp 0..7 batch pairs, r 0..63), u64 = f32x2 over batch.
// ======================================================================
#define OFF_H2    0        // [8 bp][128 j] u64      2048 floats
#define OFF_PPART 2048     // [4 hg][512 slot] u64   4096 floats
#define OFF_PPB   6144     // [512 slot] u64         1024 floats
#define OFF_PRED  7168     // [64] u64                128 floats
#define OFF_PF2   7296     // [512 slot] u64         1024 floats
#define SMEM_FLOATS 8320
#define SMEM_BYTES  (SMEM_FLOATS * 4)

__global__ void __cluster_dims__(NH, 1, 1) __launch_bounds__(256, 1)
scan_kernel(const float* __restrict__ h0g,
            const float* __restrict__ U1,
            const float* __restrict__ U2,
            const float* __restrict__ bg_g,
            const float* __restrict__ bu_g,
            const float* __restrict__ zeta,
            const float* __restrict__ nu,
            float* __restrict__ out)
{
    extern __shared__ float sm[];
    const int tid = threadIdx.x;
    const int jt  = blockIdx.x & (NH - 1);   // cluster rank = H slice
    const int bt  = blockIdx.x >> 3;         // batch tile (0..15)
    const int hgb = jt * HT;
    const int b0  = bt * BT;

    u64* h2    = (u64*)(sm + OFF_H2);
    u64* ppart = (u64*)(sm + OFF_PPART);
    u64* ppb   = (u64*)(sm + OFF_PPB);
    u64* pred  = (u64*)(sm + OFF_PRED);
    u64* pf2   = (u64*)(sm + OFF_PF2);

    // ---- h0 into smem (packed batch pairs) ----
    for (int idx = tid; idx < 8 * HT; idx += 256) {
        int bp = idx >> 7, j = idx & 127;
        float a = h0g[(size_t)(b0 + 2 * bp)     * Hh + hgb + j];
        float b = h0g[(size_t)(b0 + 2 * bp + 1) * Hh + hgb + j];
        h2[bp * HT + j] = pack2(a, b);
    }

    // ---- phase A weights in registers: U1[rA][hgb + hg*32 .. +32) ----
    const int rA = tid & 63, hg = tid >> 6;
    float wA[32];
    {
        const float* u1r = U1 + (size_t)rA * Hh + hgb + hg * 32;
        #pragma unroll
        for (int q = 0; q < 8; q++) {
            float4 v = *(const float4*)(u1r + q * 4);
            wA[q * 4 + 0] = v.x; wA[q * 4 + 1] = v.y;
            wA[q * 4 + 2] = v.z; wA[q * 4 + 3] = v.w;
        }
    }

    // ---- phase B weights in registers: U2 column for j = jB ----
    const int jB = tid & 127, bh = tid >> 7;   // bh in 0..1 -> bp range bh*4..+4
    float wB[64];
    {
        const float* u2r = U2 + (size_t)(hgb + jB) * Rr;
        #pragma unroll
        for (int q = 0; q < 16; q++) {
            float4 v = *(const float4*)(u2r + q * 4);
            wB[q * 4 + 0] = v.x; wB[q * 4 + 1] = v.y;
            wB[q * 4 + 2] = v.z; wB[q * 4 + 3] = v.w;
        }
    }
    const float bgv = bg_g[hgb + jB];
    const float buv = bu_g[hgb + jB];
    const float zs  = sigmoidf_(zeta[0]);
    const float ns  = sigmoidf_(nu[0]);
    __syncthreads();

    const uint32_t smem_base = (uint32_t)__cvta_generic_to_shared(sm);
    const uint32_t ppb_base  = smem_base + OFF_PPB  * 4u;
    const uint32_t pred_base = smem_base + OFF_PRED * 4u;

    // all-gather mapping: thread owns slots 2*tid, 2*tid+1 (same rank chunk)
    const uint32_t ag_rank = (uint32_t)(tid >> 5);
    const uint32_t ag_addr = mapa_rank(pred_base + (uint32_t)((2 * tid) & 63) * 8u, ag_rank);
    // reduce-scatter: threads 0..63, slot jt*64 + tid
    const uint32_t rs_off = ppb_base + (uint32_t)(jt * 64 + tid) * 8u;
    uint32_t rs_addr[NH];
    #pragma unroll
    for (int rk = 0; rk < NH; rk++) rs_addr[rk] = mapa_rank(rs_off, (uint32_t)rk);

    const float* wsrc0 = g_wx2 + ((size_t)b0 + bh * 8) * Hh + hgb + jB;

    for (int t = 0; t < Tt; t++) {
        // prefetch wx for epilogue: 8 batch rows at column jB
        const float* ws = wsrc0 + (size_t)t * Bb * Hh;
        float wx[8];
        #pragma unroll
        for (int k = 0; k < 8; k++) wx[k] = ws[(size_t)k * Hh];

        // ---------- phase A: partials over hg slice of 32 hh, all 8 bp ----------
        {
            u64 aA[8];
            #pragma unroll
            for (int i = 0; i < 8; i++) aA[i] = 0ull;
            #pragma unroll
            for (int k4 = 0; k4 < 32; k4 += 4) {
                u64 w0 = dup2(wA[k4 + 0]), w1 = dup2(wA[k4 + 1]);
                u64 w2 = dup2(wA[k4 + 2]), w3 = dup2(wA[k4 + 3]);
                const u64* hb = h2 + hg * 32 + k4;
                #pragma unroll
                for (int bp = 0; bp < 8; bp++) {
                    ulonglong2 p0 = *(const ulonglong2*)(hb + bp * HT);
                    ulonglong2 p1 = *(const ulonglong2*)(hb + bp * HT + 2);
                    u64 a = aA[bp];
                    a = fma2(p0.x, w0, a);
                    a = fma2(p0.y, w1, a);
                    a = fma2(p1.x, w2, a);
                    a = fma2(p1.y, w3, a);
                    aA[bp] = a;
                }
            }
            #pragma unroll
            for (int bp = 0; bp < 8; bp++)
                ppart[hg * 512 + bp * 64 + rA] = aA[bp];
        }
        __syncthreads();

        // ---------- local hg-reduce: 512 slots by 256 threads (2 each) ----------
        {
            #pragma unroll
            for (int i = 0; i < 2; i++) {
                int s = tid + i * 256;
                u64 v = add2(add2(ppart[s], ppart[512 + s]),
                             add2(ppart[1024 + s], ppart[1536 + s]));
                ppb[s] = v;
            }
        }
        cluster_sync_();

        // ---------- reduce-scatter: rank jt sums its 64-slot chunk over 8 ranks ----------
        if (tid < 64) {
            float sx = 0.0f, sy = 0.0f;
            #pragma unroll
            for (int rk = 0; rk < NH; rk++) {
                float2 v = ld_dsmem2(rs_addr[rk]);
                sx += v.x;
                sy += v.y;
            }
            pred[tid] = pack2(sx, sy);
        }
        cluster_sync_();

        // ---------- all-gather reduced chunks: 2 slots per thread (16B) ----------
        {
            float4 v = ld_dsmem4(ag_addr);
            pf2[2 * tid]     = pack2(v.x, v.y);
            pf2[2 * tid + 1] = pack2(v.z, v.w);
        }
        __syncthreads();

        // ---------- phase B (full r) + fused epilogue ----------
        {
            u64 acc0 = 0, acc1 = 0, acc2 = 0, acc3 = 0;
            const u64* pb = pf2 + bh * 4 * 64;
            #pragma unroll
            for (int r2 = 0; r2 < 64; r2 += 2) {
                u64 w0 = dup2(wB[r2]), w1 = dup2(wB[r2 + 1]);
                ulonglong2 p0 = *(const ulonglong2*)(pb + r2);
                ulonglong2 p1 = *(const ulonglong2*)(pb + 64 + r2);
                ulonglong2 p2 = *(const ulonglong2*)(pb + 128 + r2);
                ulonglong2 p3 = *(const ulonglong2*)(pb + 192 + r2);
                acc0 = fma2(p0.x, w0, acc0); acc0 = fma2(p0.y, w1, acc0);
                acc1 = fma2(p1.x, w0, acc1); acc1 = fma2(p1.y, w1, acc1);
                acc2 = fma2(p2.x, w0, acc2); acc2 = fma2(p2.y, w1, acc2);
                acc3 = fma2(p3.x, w0, acc3); acc3 = fma2(p3.y, w1, acc3);
            }

            u64 accs[4] = {acc0, acc1, acc2, acc3};
            #pragma unroll
            for (int q = 0; q < 4; q++) {
                const int bp = bh * 4 + q;
                float uh0, uh1, ho0, ho1;
                unpack2(accs[q], uh0, uh1);
                unpack2(h2[bp * HT + jB], ho0, ho1);

                float pre0 = uh0 + wx[2 * q];
                float pre1 = uh1 + wx[2 * q + 1];

                float z0 = sigmoidf_(pre0 + bgv);
                float z1 = sigmoidf_(pre1 + bgv);

                float y0 = pre0 + buv, y1 = pre1 + buv;
                float e0 = __expf(-2.0f * fabsf(y0));
                float e1 = __expf(-2.0f * fabsf(y1));
                float c0 = copysignf(__fdividef(1.0f - e0, 1.0f + e0), y0);
                float c1 = copysignf(__fdividef(1.0f - e1, 1.0f + e1), y1);

                float hn0 = fmaf(fmaf(zs, 1.0f - z0, ns), c0, z0 * ho0);
                float hn1 = fmaf(fmaf(zs, 1.0f - z1, ns), c1, z1 * ho1);

                h2[bp * HT + jB] = pack2(hn0, hn1);
                size_t ob = ((size_t)t * Bb + b0 + 2 * bp) * Hh + hgb + jB;
                out[ob]      = hn0;
                out[ob + Hh] = hn1;
            }
        }
        __syncthreads();   // h2 visible before next phase A
    }
}

// ======================================================================
// Launch
// ======================================================================
extern "C" void kernel_launch(void* const* d_in, const int* in_sizes, int n_in,
                              void* d_out, int out_size)
{
    const float* x    = (const float*)d_in[0];
    const float* h0   = (const float*)d_in[1];
    const float* W1   = (const float*)d_in[2];
    const float* W2   = (const float*)d_in[3];
    const float* U1   = (const float*)d_in[4];
    const float* U2   = (const float*)d_in[5];
    const float* bg   = (const float*)d_in[6];
    const float* bu   = (const float*)d_in[7];
    const float* zeta = (const float*)d_in[8];
    const float* nu   = (const float*)d_in[9];
    float* out = (float*)d_out;

    // 1) xw1 = x @ W1^T
    xw1_kernel<<<(Tt * Bb) / 64, 256>>>(x, W1);

    // 2) wx2 = xw1 @ W2^T
    const int wx2_smem = 2 * 64 * PM * sizeof(float);
    cudaFuncSetAttribute(wx2_kernel, cudaFuncAttributeMaxDynamicSharedMemorySize,
                         wx2_smem);
    dim3 g2((Tt * Bb) / 128, Hh / 128);
    wx2_kernel<<<g2, 256, wx2_smem>>>(W2);

    // 3) persistent cluster scan: 16 clusters x 8 CTAs = 128 CTAs
    cudaFuncSetAttribute(scan_kernel, cudaFuncAttributeMaxDynamicSharedMemorySize,
                         SMEM_BYTES);
    scan_kernel<<<(Bb / BT) * NH, 256, SMEM_BYTES>>>(h0, U1, U2, bg, bu,
                                                     zeta, nu, out);
}

// round 11
// speedup vs baseline: 1.1672x; 1.1672x over previous
#include <cuda_runtime.h>
#include <cstdint>
#include <math.h>

typedef unsigned long long u64;

// Problem constants
#define Tt 512
#define Bb 256
#define Dd 256
#define Hh 1024
#define Rr 64

// Scan tiling
#define BT 8     // batch rows per cluster (4 f32x2 pairs)
#define HT 128   // hidden slice per CTA
#define NH 8     // cluster size

// Scratch
__device__ float g_xw1[(size_t)Tt * Bb * Rr];          // 33.5 MB
__device__ float g_wx2[(size_t)Tt * Bb * Hh];          // 537 MB

// ---------------- packed f32x2 helpers ----------------
__device__ __forceinline__ u64 fma2(u64 a, u64 b, u64 c) {
    u64 d;
    asm("fma.rn.f32x2 %0, %1, %2, %3;" : "=l"(d) : "l"(a), "l"(b), "l"(c));
    return d;
}
__device__ __forceinline__ u64 add2(u64 a, u64 b) {
    u64 d;
    asm("add.rn.f32x2 %0, %1, %2;" : "=l"(d) : "l"(a), "l"(b));
    return d;
}
__device__ __forceinline__ u64 dup2(float x) {
    u64 d;
    asm("mov.b64 %0, {%1, %1};" : "=l"(d) : "f"(x));
    return d;
}
__device__ __forceinline__ u64 pack2(float x, float y) {
    u64 d;
    asm("mov.b64 %0, {%1, %2};" : "=l"(d) : "f"(x), "f"(y));
    return d;
}
__device__ __forceinline__ void unpack2(u64 v, float& x, float& y) {
    asm("mov.b64 {%0, %1}, %2;" : "=f"(x), "=f"(y) : "l"(v));
}
__device__ __forceinline__ void cluster_sync_() {
    asm volatile("barrier.cluster.arrive.aligned;" ::: "memory");
    asm volatile("barrier.cluster.wait.aligned;" ::: "memory");
}
__device__ __forceinline__ uint32_t mapa_rank(uint32_t laddr, uint32_t rank) {
    uint32_t r;
    asm("mapa.shared::cluster.u32 %0, %1, %2;" : "=r"(r) : "r"(laddr), "r"(rank));
    return r;
}
__device__ __forceinline__ float2 ld_dsmem2(uint32_t addr) {
    float2 v;
    asm volatile("ld.shared::cluster.v2.f32 {%0, %1}, [%2];"
                 : "=f"(v.x), "=f"(v.y) : "r"(addr));
    return v;
}
__device__ __forceinline__ float sigmoidf_(float x) {
    return 1.0f / (1.0f + __expf(-x));
}

// ======================================================================
// Kernel 1: xw1[m][r] = sum_d x[m][d] * W1[r][d]
// ======================================================================
__global__ void __launch_bounds__(256) xw1_kernel(const float* __restrict__ x,
                                                  const float* __restrict__ W1)
{
    __shared__ float Ast[64 * 64];
    __shared__ float Bst[64 * 64];

    const int tid = threadIdx.x;
    const int m0  = blockIdx.x * 64;
    const int tx  = tid & 15;
    const int ty  = tid >> 4;

    float acc[4][4];
    #pragma unroll
    for (int i = 0; i < 4; i++)
        #pragma unroll
        for (int j = 0; j < 4; j++) acc[i][j] = 0.0f;

    for (int kk = 0; kk < Dd; kk += 64) {
        #pragma unroll
        for (int i = 0; i < 4; i++) {
            int s   = tid + i * 256;
            int row = s >> 4;
            int kq  = s & 15;
            float4 a = *(const float4*)(x  + (size_t)(m0 + row) * Dd + kk + kq * 4);
            Ast[(kq * 4 + 0) * 64 + row] = a.x;
            Ast[(kq * 4 + 1) * 64 + row] = a.y;
            Ast[(kq * 4 + 2) * 64 + row] = a.z;
            Ast[(kq * 4 + 3) * 64 + row] = a.w;
            float4 b = *(const float4*)(W1 + (size_t)row * Dd + kk + kq * 4);
            Bst[(kq * 4 + 0) * 64 + row] = b.x;
            Bst[(kq * 4 + 1) * 64 + row] = b.y;
            Bst[(kq * 4 + 2) * 64 + row] = b.z;
            Bst[(kq * 4 + 3) * 64 + row] = b.w;
        }
        __syncthreads();
        #pragma unroll
        for (int k = 0; k < 64; k++) {
            float4 a = *(const float4*)(Ast + k * 64 + ty * 4);
            float4 b = *(const float4*)(Bst + k * 64 + tx * 4);
            acc[0][0] = fmaf(a.x, b.x, acc[0][0]); acc[0][1] = fmaf(a.x, b.y, acc[0][1]);
            acc[0][2] = fmaf(a.x, b.z, acc[0][2]); acc[0][3] = fmaf(a.x, b.w, acc[0][3]);
            acc[1][0] = fmaf(a.y, b.x, acc[1][0]); acc[1][1] = fmaf(a.y, b.y, acc[1][1]);
            acc[1][2] = fmaf(a.y, b.z, acc[1][2]); acc[1][3] = fmaf(a.y, b.w, acc[1][3]);
            acc[2][0] = fmaf(a.z, b.x, acc[2][0]); acc[2][1] = fmaf(a.z, b.y, acc[2][1]);
            acc[2][2] = fmaf(a.z, b.z, acc[2][2]); acc[2][3] = fmaf(a.z, b.w, acc[2][3]);
            acc[3][0] = fmaf(a.w, b.x, acc[3][0]); acc[3][1] = fmaf(a.w, b.y, acc[3][1]);
            acc[3][2] = fmaf(a.w, b.z, acc[3][2]); acc[3][3] = fmaf(a.w, b.w, acc[3][3]);
        }
        __syncthreads();
    }

    #pragma unroll
    for (int i = 0; i < 4; i++) {
        float4 o = make_float4(acc[i][0], acc[i][1], acc[i][2], acc[i][3]);
        *(float4*)(g_xw1 + (size_t)(m0 + ty * 4 + i) * Rr + tx * 4) = o;
    }
}

// ======================================================================
// Kernel 2: wx2[m][h] = sum_r xw1[m][r] * W2[h][r]
// ======================================================================
#define PM 132
__global__ void __launch_bounds__(256) wx2_kernel(const float* __restrict__ W2)
{
    extern __shared__ float smg[];
    float* Ast = smg;
    float* Bst = smg + 64 * PM;

    const int tid = threadIdx.x;
    const int m0  = blockIdx.x * 128;
    const int h0  = blockIdx.y * 128;

    #pragma unroll
    for (int i = 0; i < 8; i++) {
        int s  = tid + i * 256;
        int mm = s >> 4;
        int rq = s & 15;
        float4 a = *(const float4*)(g_xw1 + (size_t)(m0 + mm) * 64 + rq * 4);
        Ast[(rq * 4 + 0) * PM + mm] = a.x;
        Ast[(rq * 4 + 1) * PM + mm] = a.y;
        Ast[(rq * 4 + 2) * PM + mm] = a.z;
        Ast[(rq * 4 + 3) * PM + mm] = a.w;
        float4 b = *(const float4*)(W2 + (size_t)(h0 + mm) * 64 + rq * 4);
        Bst[(rq * 4 + 0) * PM + mm] = b.x;
        Bst[(rq * 4 + 1) * PM + mm] = b.y;
        Bst[(rq * 4 + 2) * PM + mm] = b.z;
        Bst[(rq * 4 + 3) * PM + mm] = b.w;
    }
    __syncthreads();

    const int tx = tid & 15;
    const int ty = tid >> 4;

    u64 acc[4][8];
    #pragma unroll
    for (int i = 0; i < 4; i++)
        #pragma unroll
        for (int j = 0; j < 8; j++) acc[i][j] = 0ull;

    #pragma unroll 4
    for (int k = 0; k < 64; k++) {
        const u64* ap = (const u64*)(Ast + k * PM + ty * 8);
        u64 a0 = ap[0], a1 = ap[1], a2 = ap[2], a3 = ap[3];
        const float* bp = Bst + k * PM + tx * 8;
        float4 b0 = *(const float4*)(bp);
        float4 b1 = *(const float4*)(bp + 4);
        float bs[8] = {b0.x, b0.y, b0.z, b0.w, b1.x, b1.y, b1.z, b1.w};
        #pragma unroll
        for (int j = 0; j < 8; j++) {
            u64 bd = dup2(bs[j]);
            acc[0][j] = fma2(a0, bd, acc[0][j]);
            acc[1][j] = fma2(a1, bd, acc[1][j]);
            acc[2][j] = fma2(a2, bd, acc[2][j]);
            acc[3][j] = fma2(a3, bd, acc[3][j]);
        }
    }

    #pragma unroll
    for (int i = 0; i < 4; i++) {
        float lo[8], hi[8];
        #pragma unroll
        for (int j = 0; j < 8; j++) unpack2(acc[i][j], lo[j], hi[j]);
        size_t base0 = (size_t)(m0 + ty * 8 + 2 * i)     * Hh + h0 + tx * 8;
        size_t base1 = (size_t)(m0 + ty * 8 + 2 * i + 1) * Hh + h0 + tx * 8;
        *(float4*)(g_wx2 + base0)     = make_float4(lo[0], lo[1], lo[2], lo[3]);
        *(float4*)(g_wx2 + base0 + 4) = make_float4(lo[4], lo[5], lo[6], lo[7]);
        *(float4*)(g_wx2 + base1)     = make_float4(hi[0], hi[1], hi[2], hi[3]);
        *(float4*)(g_wx2 + base1 + 4) = make_float4(hi[4], hi[5], hi[6], hi[7]);
    }
}

// ======================================================================
// Kernel 3: persistent cluster scan. 32 clusters x 8 CTAs = 256 CTAs,
// 2 CTAs/SM (occ 2 hides sync + DSMEM latency). BT=8 (4 f32x2 pairs).
// U1 slice in smem [r][hh] (pitch 132); U2 column in 64 registers.
// Exchange per step: local hg-reduce -> csync -> DSMEM reduce-scatter
// (rank jt sums its 32-slot chunk over 8 ranks) -> csync -> all-gather.
// slot = bp*64 + r  (bp 0..3 batch pairs, r 0..63), u64 = f32x2 over batch.
// ======================================================================
#define U1P 132

// float offsets in dynamic smem (all 16B-aligned)
#define OFF_U1T   0        // [64 r][U1P]          8448 floats
#define OFF_H2    8448     // [4 bp][128 j] u64    1024 floats
#define OFF_PPART 9472     // [4 hg][256 slot] u64 2048 floats
#define OFF_PPB   11520    // [256 slot] u64        512 floats (DSMEM src, RS)
#define OFF_PRED  12032    // [32] u64               64 floats (DSMEM src, AG)
#define OFF_PF2   12096    // [256 slot] u64        512 floats
#define SMEM_FLOATS 12608
#define SMEM_BYTES  (SMEM_FLOATS * 4)

__global__ void __cluster_dims__(NH, 1, 1) __launch_bounds__(256, 2)
scan_kernel(const float* __restrict__ h0g,
            const float* __restrict__ U1,
            const float* __restrict__ U2,
            const float* __restrict__ bg_g,
            const float* __restrict__ bu_g,
            const float* __restrict__ zeta,
            const float* __restrict__ nu,
            float* __restrict__ out)
{
    extern __shared__ float sm[];
    const int tid = threadIdx.x;
    const int jt  = blockIdx.x & (NH - 1);   // cluster rank = H slice
    const int bt  = blockIdx.x >> 3;         // batch tile (0..31)
    const int hgb = jt * HT;
    const int b0  = bt * BT;

    u64* h2    = (u64*)(sm + OFF_H2);
    u64* ppart = (u64*)(sm + OFF_PPART);
    u64* ppb   = (u64*)(sm + OFF_PPB);
    u64* pred  = (u64*)(sm + OFF_PRED);
    u64* pf2   = (u64*)(sm + OFF_PF2);

    // ---- one-time loads ----
    for (int idx = tid; idx < 64 * HT; idx += 256) {
        int r = idx >> 7, hh = idx & 127;
        sm[OFF_U1T + r * U1P + hh] = U1[(size_t)r * Hh + hgb + hh];   // [r][hh]
    }
    for (int idx = tid; idx < 4 * HT; idx += 256) {
        int bp = idx >> 7, j = idx & 127;
        float a = h0g[(size_t)(b0 + 2 * bp)     * Hh + hgb + j];
        float b = h0g[(size_t)(b0 + 2 * bp + 1) * Hh + hgb + j];
        h2[bp * HT + j] = pack2(a, b);
    }

    // phase B: thread = (jB 0..127, bh 0..1); owns bp = bh*2, bh*2+1
    const int jB = tid & 127, bh = tid >> 7;
    float wB[64];
    {
        const float* u2r = U2 + (size_t)(hgb + jB) * Rr;
        #pragma unroll
        for (int q = 0; q < 16; q++) {
            float4 v = *(const float4*)(u2r + q * 4);
            wB[q * 4 + 0] = v.x; wB[q * 4 + 1] = v.y;
            wB[q * 4 + 2] = v.z; wB[q * 4 + 3] = v.w;
        }
    }
    const float bgv = bg_g[hgb + jB];
    const float buv = bu_g[hgb + jB];
    const float zs  = sigmoidf_(zeta[0]);
    const float ns  = sigmoidf_(nu[0]);
    __syncthreads();

    const uint32_t smem_base = (uint32_t)__cvta_generic_to_shared(sm);
    const uint32_t ppb_base  = smem_base + OFF_PPB  * 4u;
    const uint32_t pred_base = smem_base + OFF_PRED * 4u;

    // phase A: thread = (rA 0..63, hg 0..3); hg slice of 32 hh
    const int rA = tid & 63, hg = tid >> 6;
    const float* u1row = sm + OFF_U1T + rA * U1P + hg * 32;

    // reduce-scatter: threads 0..31 handle slot jt*32 + tid over 8 ranks
    uint32_t rs_addr[NH];
    {
        const uint32_t rs_off = ppb_base + (uint32_t)(jt * 32 + (tid & 31)) * 8u;
        #pragma unroll
        for (int rk = 0; rk < NH; rk++) rs_addr[rk] = mapa_rank(rs_off, (uint32_t)rk);
    }
    // all-gather: thread tid pulls global slot tid from rank tid>>5
    const uint32_t ag_addr = mapa_rank(pred_base + (uint32_t)(tid & 31) * 8u,
                                       (uint32_t)(tid >> 5));

    const float* wsrc0 = g_wx2 + ((size_t)b0 + bh * 4) * Hh + hgb + jB;

    for (int t = 0; t < Tt; t++) {
        // prefetch wx for epilogue: 4 batch rows at column jB
        const float* ws = wsrc0 + (size_t)t * Bb * Hh;
        float wx0 = ws[0];
        float wx1 = ws[Hh];
        float wx2 = ws[2 * Hh];
        float wx3 = ws[3 * Hh];

        // ---------- phase A: partials over hg slice of 32 hh, 4 bp ----------
        {
            u64 a0 = 0, a1 = 0, a2 = 0, a3 = 0;
            #pragma unroll
            for (int k4 = 0; k4 < 32; k4 += 4) {
                float4 w4 = *(const float4*)(u1row + k4);
                u64 w0 = dup2(w4.x), w1 = dup2(w4.y);
                u64 w2 = dup2(w4.z), w3 = dup2(w4.w);
                const u64* hb = h2 + hg * 32 + k4;
                {
                    ulonglong2 p0 = *(const ulonglong2*)(hb);
                    ulonglong2 p1 = *(const ulonglong2*)(hb + 2);
                    a0 = fma2(p0.x, w0, a0); a0 = fma2(p0.y, w1, a0);
                    a0 = fma2(p1.x, w2, a0); a0 = fma2(p1.y, w3, a0);
                }
                {
                    ulonglong2 p0 = *(const ulonglong2*)(hb + HT);
                    ulonglong2 p1 = *(const ulonglong2*)(hb + HT + 2);
                    a1 = fma2(p0.x, w0, a1); a1 = fma2(p0.y, w1, a1);
                    a1 = fma2(p1.x, w2, a1); a1 = fma2(p1.y, w3, a1);
                }
                {
                    ulonglong2 p0 = *(const ulonglong2*)(hb + 2 * HT);
                    ulonglong2 p1 = *(const ulonglong2*)(hb + 2 * HT + 2);
                    a2 = fma2(p0.x, w0, a2); a2 = fma2(p0.y, w1, a2);
                    a2 = fma2(p1.x, w2, a2); a2 = fma2(p1.y, w3, a2);
                }
                {
                    ulonglong2 p0 = *(const ulonglong2*)(hb + 3 * HT);
                    ulonglong2 p1 = *(const ulonglong2*)(hb + 3 * HT + 2);
                    a3 = fma2(p0.x, w0, a3); a3 = fma2(p0.y, w1, a3);
                    a3 = fma2(p1.x, w2, a3); a3 = fma2(p1.y, w3, a3);
                }
            }
            ppart[hg * 256 +   0 + rA] = a0;
            ppart[hg * 256 +  64 + rA] = a1;
            ppart[hg * 256 + 128 + rA] = a2;
            ppart[hg * 256 + 192 + rA] = a3;
        }
        __syncthreads();

        // ---------- local hg-reduce: 256 slots, 1 per thread ----------
        {
            u64 v = add2(add2(ppart[tid], ppart[256 + tid]),
                         add2(ppart[512 + tid], ppart[768 + tid]));
            ppb[tid] = v;
        }
        cluster_sync_();

        // ---------- reduce-scatter: rank jt sums its 32-slot chunk ----------
        if (tid < 32) {
            float sx = 0.0f, sy = 0.0f;
            #pragma unroll
            for (int rk = 0; rk < NH; rk++) {
                float2 v = ld_dsmem2(rs_addr[rk]);
                sx += v.x;
                sy += v.y;
            }
            pred[tid] = pack2(sx, sy);
        }
        cluster_sync_();

        // ---------- all-gather: 1 slot per thread ----------
        {
            float2 v = ld_dsmem2(ag_addr);
            pf2[tid] = pack2(v.x, v.y);
        }
        __syncthreads();

        // ---------- phase B (full r, 2 bp) + fused epilogue ----------
        {
            u64 acc0 = 0, acc1 = 0;
            const u64* pb = pf2 + bh * 2 * 64;
            #pragma unroll
            for (int r2 = 0; r2 < 64; r2 += 2) {
                u64 w0 = dup2(wB[r2]), w1 = dup2(wB[r2 + 1]);
                ulonglong2 p0 = *(const ulonglong2*)(pb + r2);
                ulonglong2 p1 = *(const ulonglong2*)(pb + 64 + r2);
                acc0 = fma2(p0.x, w0, acc0); acc0 = fma2(p0.y, w1, acc0);
                acc1 = fma2(p1.x, w0, acc1); acc1 = fma2(p1.y, w1, acc1);
            }

            u64 accs[2] = {acc0, acc1};
            float wxs[4] = {wx0, wx1, wx2, wx3};
            #pragma unroll
            for (int q = 0; q < 2; q++) {
                const int bp = bh * 2 + q;
                float uh0, uh1, ho0, ho1;
                unpack2(accs[q], uh0, uh1);
                unpack2(h2[bp * HT + jB], ho0, ho1);

                float pre0 = uh0 + wxs[2 * q];
                float pre1 = uh1 + wxs[2 * q + 1];

                float z0 = sigmoidf_(pre0 + bgv);
                float z1 = sigmoidf_(pre1 + bgv);

                float y0 = pre0 + buv, y1 = pre1 + buv;
                float e0 = __expf(-2.0f * fabsf(y0));
                float e1 = __expf(-2.0f * fabsf(y1));
                float c0 = copysignf(__fdividef(1.0f - e0, 1.0f + e0), y0);
                float c1 = copysignf(__fdividef(1.0f - e1, 1.0f + e1), y1);

                float hn0 = fmaf(fmaf(zs, 1.0f - z0, ns), c0, z0 * ho0);
                float hn1 = fmaf(fmaf(zs, 1.0f - z1, ns), c1, z1 * ho1);

                h2[bp * HT + jB] = pack2(hn0, hn1);
                size_t ob = ((size_t)t * Bb + b0 + 2 * bp) * Hh + hgb + jB;
                out[ob]      = hn0;
                out[ob + Hh] = hn1;
            }
        }
        __syncthreads();   // h2 visible before next phase A
    }
}

// ======================================================================
// Launch
// ======================================================================
extern "C" void kernel_launch(void* const* d_in, const int* in_sizes, int n_in,
                              void* d_out, int out_size)
{
    const float* x    = (const float*)d_in[0];
    const float* h0   = (const float*)d_in[1];
    const float* W1   = (const float*)d_in[2];
    const float* W2   = (const float*)d_in[3];
    const float* U1   = (const float*)d_in[4];
    const float* U2   = (const float*)d_in[5];
    const float* bg   = (const float*)d_in[6];
    const float* bu   = (const float*)d_in[7];
    const float* zeta = (const float*)d_in[8];
    const float* nu   = (const float*)d_in[9];
    float* out = (float*)d_out;

    // 1) xw1 = x @ W1^T
    xw1_kernel<<<(Tt * Bb) / 64, 256>>>(x, W1);

    // 2) wx2 = xw1 @ W2^T
    const int wx2_smem = 2 * 64 * PM * sizeof(float);
    cudaFuncSetAttribute(wx2_kernel, cudaFuncAttributeMaxDynamicSharedMemorySize,
                         wx2_smem);
    dim3 g2((Tt * Bb) / 128, Hh / 128);
    wx2_kernel<<<g2, 256, wx2_smem>>>(W2);

    // 3) persistent cluster scan: 32 clusters x 8 CTAs = 256 CTAs, occ 2
    cudaFuncSetAttribute(scan_kernel, cudaFuncAttributeMaxDynamicSharedMemorySize,
                         SMEM_BYTES);
    scan_kernel<<<(Bb / BT) * NH, 256, SMEM_BYTES>>>(h0, U1, U2, bg, bu,
                                                     zeta, nu, out);
}

// round 12
// speedup vs baseline: 1.2518x; 1.0724x over previous
#include <cuda_runtime.h>
#include <cstdint>
#include <math.h>

typedef unsigned long long u64;

// Problem constants
#define Tt 512
#define Bb 256
#define Dd 256
#define Hh 1024
#define Rr 64

// Scan tiling
#define BT 8     // batch rows per cluster (4 f32x2 pairs)
#define HT 128   // hidden slice per CTA
#define NH 8     // cluster size

// Scratch
__device__ float g_xw1[(size_t)Tt * Bb * Rr];          // 33.5 MB
__device__ float g_wx2[(size_t)Tt * Bb * Hh];          // 537 MB

// ---------------- packed f32x2 helpers ----------------
__device__ __forceinline__ u64 fma2(u64 a, u64 b, u64 c) {
    u64 d;
    asm("fma.rn.f32x2 %0, %1, %2, %3;" : "=l"(d) : "l"(a), "l"(b), "l"(c));
    return d;
}
__device__ __forceinline__ u64 add2(u64 a, u64 b) {
    u64 d;
    asm("add.rn.f32x2 %0, %1, %2;" : "=l"(d) : "l"(a), "l"(b));
    return d;
}
__device__ __forceinline__ u64 dup2(float x) {
    u64 d;
    asm("mov.b64 %0, {%1, %1};" : "=l"(d) : "f"(x));
    return d;
}
__device__ __forceinline__ u64 pack2(float x, float y) {
    u64 d;
    asm("mov.b64 %0, {%1, %2};" : "=l"(d) : "f"(x), "f"(y));
    return d;
}
__device__ __forceinline__ void unpack2(u64 v, float& x, float& y) {
    asm("mov.b64 {%0, %1}, %2;" : "=f"(x), "=f"(y) : "l"(v));
}
__device__ __forceinline__ void cluster_sync_() {
    asm volatile("barrier.cluster.arrive.aligned;" ::: "memory");
    asm volatile("barrier.cluster.wait.aligned;" ::: "memory");
}
__device__ __forceinline__ uint32_t mapa_rank(uint32_t laddr, uint32_t rank) {
    uint32_t r;
    asm("mapa.shared::cluster.u32 %0, %1, %2;" : "=r"(r) : "r"(laddr), "r"(rank));
    return r;
}
__device__ __forceinline__ float2 ld_dsmem2(uint32_t addr) {
    float2 v;
    asm volatile("ld.shared::cluster.v2.f32 {%0, %1}, [%2];"
                 : "=f"(v.x), "=f"(v.y) : "r"(addr));
    return v;
}
__device__ __forceinline__ u64 shflx1(u64 v) {
    return __shfl_xor_sync(0xffffffffu, v, 1);
}
__device__ __forceinline__ float sigmoidf_(float x) {
    return 1.0f / (1.0f + __expf(-x));
}

// ======================================================================
// Kernel 1: xw1[m][r] = sum_d x[m][d] * W1[r][d]
// ======================================================================
__global__ void __launch_bounds__(256) xw1_kernel(const float* __restrict__ x,
                                                  const float* __restrict__ W1)
{
    __shared__ float Ast[64 * 64];
    __shared__ float Bst[64 * 64];

    const int tid = threadIdx.x;
    const int m0  = blockIdx.x * 64;
    const int tx  = tid & 15;
    const int ty  = tid >> 4;

    float acc[4][4];
    #pragma unroll
    for (int i = 0; i < 4; i++)
        #pragma unroll
        for (int j = 0; j < 4; j++) acc[i][j] = 0.0f;

    for (int kk = 0; kk < Dd; kk += 64) {
        #pragma unroll
        for (int i = 0; i < 4; i++) {
            int s   = tid + i * 256;
            int row = s >> 4;
            int kq  = s & 15;
            float4 a = *(const float4*)(x  + (size_t)(m0 + row) * Dd + kk + kq * 4);
            Ast[(kq * 4 + 0) * 64 + row] = a.x;
            Ast[(kq * 4 + 1) * 64 + row] = a.y;
            Ast[(kq * 4 + 2) * 64 + row] = a.z;
            Ast[(kq * 4 + 3) * 64 + row] = a.w;
            float4 b = *(const float4*)(W1 + (size_t)row * Dd + kk + kq * 4);
            Bst[(kq * 4 + 0) * 64 + row] = b.x;
            Bst[(kq * 4 + 1) * 64 + row] = b.y;
            Bst[(kq * 4 + 2) * 64 + row] = b.z;
            Bst[(kq * 4 + 3) * 64 + row] = b.w;
        }
        __syncthreads();
        #pragma unroll
        for (int k = 0; k < 64; k++) {
            float4 a = *(const float4*)(Ast + k * 64 + ty * 4);
            float4 b = *(const float4*)(Bst + k * 64 + tx * 4);
            acc[0][0] = fmaf(a.x, b.x, acc[0][0]); acc[0][1] = fmaf(a.x, b.y, acc[0][1]);
            acc[0][2] = fmaf(a.x, b.z, acc[0][2]); acc[0][3] = fmaf(a.x, b.w, acc[0][3]);
            acc[1][0] = fmaf(a.y, b.x, acc[1][0]); acc[1][1] = fmaf(a.y, b.y, acc[1][1]);
            acc[1][2] = fmaf(a.y, b.z, acc[1][2]); acc[1][3] = fmaf(a.y, b.w, acc[1][3]);
            acc[2][0] = fmaf(a.z, b.x, acc[2][0]); acc[2][1] = fmaf(a.z, b.y, acc[2][1]);
            acc[2][2] = fmaf(a.z, b.z, acc[2][2]); acc[2][3] = fmaf(a.z, b.w, acc[2][3]);
            acc[3][0] = fmaf(a.w, b.x, acc[3][0]); acc[3][1] = fmaf(a.w, b.y, acc[3][1]);
            acc[3][2] = fmaf(a.w, b.z, acc[3][2]); acc[3][3] = fmaf(a.w, b.w, acc[3][3]);
        }
        __syncthreads();
    }

    #pragma unroll
    for (int i = 0; i < 4; i++) {
        float4 o = make_float4(acc[i][0], acc[i][1], acc[i][2], acc[i][3]);
        *(float4*)(g_xw1 + (size_t)(m0 + ty * 4 + i) * Rr + tx * 4) = o;
    }
}

// ======================================================================
// Kernel 2: wx2[m][h] = sum_r xw1[m][r] * W2[h][r]
// ======================================================================
#define PM 132
__global__ void __launch_bounds__(256) wx2_kernel(const float* __restrict__ W2)
{
    extern __shared__ float smg[];
    float* Ast = smg;
    float* Bst = smg + 64 * PM;

    const int tid = threadIdx.x;
    const int m0  = blockIdx.x * 128;
    const int h0  = blockIdx.y * 128;

    #pragma unroll
    for (int i = 0; i < 8; i++) {
        int s  = tid + i * 256;
        int mm = s >> 4;
        int rq = s & 15;
        float4 a = *(const float4*)(g_xw1 + (size_t)(m0 + mm) * 64 + rq * 4);
        Ast[(rq * 4 + 0) * PM + mm] = a.x;
        Ast[(rq * 4 + 1) * PM + mm] = a.y;
        Ast[(rq * 4 + 2) * PM + mm] = a.z;
        Ast[(rq * 4 + 3) * PM + mm] = a.w;
        float4 b = *(const float4*)(W2 + (size_t)(h0 + mm) * 64 + rq * 4);
        Bst[(rq * 4 + 0) * PM + mm] = b.x;
        Bst[(rq * 4 + 1) * PM + mm] = b.y;
        Bst[(rq * 4 + 2) * PM + mm] = b.z;
        Bst[(rq * 4 + 3) * PM + mm] = b.w;
    }
    __syncthreads();

    const int tx = tid & 15;
    const int ty = tid >> 4;

    u64 acc[4][8];
    #pragma unroll
    for (int i = 0; i < 4; i++)
        #pragma unroll
        for (int j = 0; j < 8; j++) acc[i][j] = 0ull;

    #pragma unroll 4
    for (int k = 0; k < 64; k++) {
        const u64* ap = (const u64*)(Ast + k * PM + ty * 8);
        u64 a0 = ap[0], a1 = ap[1], a2 = ap[2], a3 = ap[3];
        const float* bp = Bst + k * PM + tx * 8;
        float4 b0 = *(const float4*)(bp);
        float4 b1 = *(const float4*)(bp + 4);
        float bs[8] = {b0.x, b0.y, b0.z, b0.w, b1.x, b1.y, b1.z, b1.w};
        #pragma unroll
        for (int j = 0; j < 8; j++) {
            u64 bd = dup2(bs[j]);
            acc[0][j] = fma2(a0, bd, acc[0][j]);
            acc[1][j] = fma2(a1, bd, acc[1][j]);
            acc[2][j] = fma2(a2, bd, acc[2][j]);
            acc[3][j] = fma2(a3, bd, acc[3][j]);
        }
    }

    #pragma unroll
    for (int i = 0; i < 4; i++) {
        float lo[8], hi[8];
        #pragma unroll
        for (int j = 0; j < 8; j++) unpack2(acc[i][j], lo[j], hi[j]);
        size_t base0 = (size_t)(m0 + ty * 8 + 2 * i)     * Hh + h0 + tx * 8;
        size_t base1 = (size_t)(m0 + ty * 8 + 2 * i + 1) * Hh + h0 + tx * 8;
        *(float4*)(g_wx2 + base0)     = make_float4(lo[0], lo[1], lo[2], lo[3]);
        *(float4*)(g_wx2 + base0 + 4) = make_float4(lo[4], lo[5], lo[6], lo[7]);
        *(float4*)(g_wx2 + base1)     = make_float4(hi[0], hi[1], hi[2], hi[3]);
        *(float4*)(g_wx2 + base1 + 4) = make_float4(hi[4], hi[5], hi[6], hi[7]);
    }
}

// ======================================================================
// Kernel 3: persistent cluster scan. 32 clusters x 8 CTAs = 256 CTAs,
// occ 2. BT=8. One cluster.sync per step. ppb double-buffered.
// Phase B threads: (j = tid>>1, half = tid&1); each accumulates its
// 32-r half for all 4 batch pairs, shfl_xor(1) combines halves in-warp,
// epilogue fused (no red buffer, 3 bars + 1 csync per step).
// slot = bp*64 + r  (bp 0..3 batch pairs, r 0..63), u64 = f32x2 over batch.
// ======================================================================
#define U1P 132
#define U2P 68

// float offsets in dynamic smem (all 16B-aligned)
#define OFF_U1T   0        // [64 r][U1P]            8448 floats
#define OFF_U2T   8448     // [128 j][U2P]           8704 floats
#define OFF_H2    17152    // [4 bp][128 j] u64      1024 floats
#define OFF_PPART 18176    // [4 hg][256 slot] u64   2048 floats
#define OFF_PPB   20224    // [2][256 slot] u64      1024 floats (DSMEM src)
#define OFF_PF2   21248    // [256 slot] u64          512 floats
#define SMEM_FLOATS 21760
#define SMEM_BYTES  (SMEM_FLOATS * 4)

__global__ void __cluster_dims__(NH, 1, 1) __launch_bounds__(256, 2)
scan_kernel(const float* __restrict__ h0g,
            const float* __restrict__ U1,
            const float* __restrict__ U2,
            const float* __restrict__ bg_g,
            const float* __restrict__ bu_g,
            const float* __restrict__ zeta,
            const float* __restrict__ nu,
            float* __restrict__ out)
{
    extern __shared__ float sm[];
    const int tid = threadIdx.x;
    const int jt  = blockIdx.x & (NH - 1);   // cluster rank = H slice
    const int bt  = blockIdx.x >> 3;         // batch tile (0..31)
    const int hgb = jt * HT;
    const int b0  = bt * BT;

    u64* h2    = (u64*)(sm + OFF_H2);
    u64* ppart = (u64*)(sm + OFF_PPART);
    u64* ppb   = (u64*)(sm + OFF_PPB);
    u64* pf2   = (u64*)(sm + OFF_PF2);

    // ---- one-time loads ----
    for (int idx = tid; idx < 64 * HT; idx += 256) {
        int r = idx >> 7, hh = idx & 127;
        sm[OFF_U1T + r * U1P + hh] = U1[(size_t)r * Hh + hgb + hh];   // [r][hh]
    }
    for (int idx = tid; idx < HT * 64; idx += 256) {
        int j = idx >> 6, r = idx & 63;
        sm[OFF_U2T + j * U2P + r] = U2[(size_t)(hgb + j) * Rr + r];   // [j][r]
    }
    for (int idx = tid; idx < 4 * HT; idx += 256) {
        int bp = idx >> 7, j = idx & 127;
        float a = h0g[(size_t)(b0 + 2 * bp)     * Hh + hgb + j];
        float b = h0g[(size_t)(b0 + 2 * bp + 1) * Hh + hgb + j];
        h2[bp * HT + j] = pack2(a, b);
    }

    // phase B mapping: thread = (jp 0..127, bh 0..1); bh = r-half & lane parity
    const int jp = tid >> 1, bh = tid & 1;
    const float* u2row = sm + OFF_U2T + jp * U2P + bh * 32;
    const float bgv = bg_g[hgb + jp];
    const float buv = bu_g[hgb + jp];
    const float zs  = sigmoidf_(zeta[0]);
    const float ns  = sigmoidf_(nu[0]);
    __syncthreads();

    const uint32_t smem_base = (uint32_t)__cvta_generic_to_shared(sm);

    // phase A mapping: thread = (rA 0..63, hg 0..3)
    const int rA = tid & 63, hg = tid >> 6;
    const float* u1row = sm + OFF_U1T + rA * U1P + hg * 32;

    // DSMEM rank bases (linear aperture: base + byte offset)
    uint32_t rkb[NH];
    #pragma unroll
    for (int rk = 0; rk < NH; rk++) rkb[rk] = mapa_rank(smem_base, rk);

    // epilogue wx source: 4 batch rows (bh*4 .. bh*4+3) at column jp
    const float* wsrc0 = g_wx2 + ((size_t)b0 + bh * 4) * Hh + hgb + jp;

    for (int t = 0; t < Tt; t++) {
        const int cur = t & 1;

        // prefetch wx for epilogue
        const float* ws = wsrc0 + (size_t)t * Bb * Hh;
        float wx0 = ws[0];
        float wx1 = ws[Hh];
        float wx2 = ws[2 * Hh];
        float wx3 = ws[3 * Hh];

        // ---------- phase A: partials over hg slice of 32 hh, 4 bp ----------
        {
            u64 a0 = 0, a1 = 0, a2 = 0, a3 = 0;
            #pragma unroll
            for (int k4 = 0; k4 < 32; k4 += 4) {
                float4 w4 = *(const float4*)(u1row + k4);
                u64 w0 = dup2(w4.x), w1 = dup2(w4.y);
                u64 w2 = dup2(w4.z), w3 = dup2(w4.w);
                const u64* hb = h2 + hg * 32 + k4;
                {
                    ulonglong2 p0 = *(const ulonglong2*)(hb);
                    ulonglong2 p1 = *(const ulonglong2*)(hb + 2);
                    a0 = fma2(p0.x, w0, a0); a0 = fma2(p0.y, w1, a0);
                    a0 = fma2(p1.x, w2, a0); a0 = fma2(p1.y, w3, a0);
                }
                {
                    ulonglong2 p0 = *(const ulonglong2*)(hb + HT);
                    ulonglong2 p1 = *(const ulonglong2*)(hb + HT + 2);
                    a1 = fma2(p0.x, w0, a1); a1 = fma2(p0.y, w1, a1);
                    a1 = fma2(p1.x, w2, a1); a1 = fma2(p1.y, w3, a1);
                }
                {
                    ulonglong2 p0 = *(const ulonglong2*)(hb + 2 * HT);
                    ulonglong2 p1 = *(const ulonglong2*)(hb + 2 * HT + 2);
                    a2 = fma2(p0.x, w0, a2); a2 = fma2(p0.y, w1, a2);
                    a2 = fma2(p1.x, w2, a2); a2 = fma2(p1.y, w3, a2);
                }
                {
                    ulonglong2 p0 = *(const ulonglong2*)(hb + 3 * HT);
                    ulonglong2 p1 = *(const ulonglong2*)(hb + 3 * HT + 2);
                    a3 = fma2(p0.x, w0, a3); a3 = fma2(p0.y, w1, a3);
                    a3 = fma2(p1.x, w2, a3); a3 = fma2(p1.y, w3, a3);
                }
            }
            ppart[hg * 256 +   0 + rA] = a0;
            ppart[hg * 256 +  64 + rA] = a1;
            ppart[hg * 256 + 128 + rA] = a2;
            ppart[hg * 256 + 192 + rA] = a3;
        }
        __syncthreads();                                   // bar 1

        // ---------- local hg-reduce into double-buffered DSMEM src ----------
        {
            u64 v = add2(add2(ppart[tid], ppart[256 + tid]),
                         add2(ppart[512 + tid], ppart[768 + tid]));
            ppb[cur * 256 + tid] = v;
        }
        cluster_sync_();                                    // cluster sync

        // ---------- all-gather: thread tid sums slot tid over 8 ranks ----------
        {
            const uint32_t off = (uint32_t)(OFF_PPB * 4)
                               + (uint32_t)(cur * 256 + tid) * 8u;
            float sx = 0.0f, sy = 0.0f;
            #pragma unroll
            for (int rk = 0; rk < NH; rk++) {
                float2 v = ld_dsmem2(rkb[rk] + off);
                sx += v.x;
                sy += v.y;
            }
            pf2[tid] = pack2(sx, sy);
        }
        __syncthreads();                                   // bar 2

        // ---------- phase B (r-half, 4 bp) + shfl combine + fused epilogue ----------
        {
            u64 acc0 = 0, acc1 = 0, acc2 = 0, acc3 = 0;
            #pragma unroll
            for (int q = 0; q < 32; q += 4) {
                float4 u4 = *(const float4*)(u2row + q);
                u64 w0 = dup2(u4.x), w1 = dup2(u4.y);
                u64 w2 = dup2(u4.z), w3 = dup2(u4.w);
                const u64* pb = pf2 + bh * 32 + q;
                {
                    ulonglong2 p0 = *(const ulonglong2*)(pb);
                    ulonglong2 p1 = *(const ulonglong2*)(pb + 2);
                    acc0 = fma2(p0.x, w0, acc0); acc0 = fma2(p0.y, w1, acc0);
                    acc0 = fma2(p1.x, w2, acc0); acc0 = fma2(p1.y, w3, acc0);
                }
                {
                    ulonglong2 p0 = *(const ulonglong2*)(pb + 64);
                    ulonglong2 p1 = *(const ulonglong2*)(pb + 66);
                    acc1 = fma2(p0.x, w0, acc1); acc1 = fma2(p0.y, w1, acc1);
                    acc1 = fma2(p1.x, w2, acc1); acc1 = fma2(p1.y, w3, acc1);
                }
                {
                    ulonglong2 p0 = *(const ulonglong2*)(pb + 128);
                    ulonglong2 p1 = *(const ulonglong2*)(pb + 130);
                    acc2 = fma2(p0.x, w0, acc2); acc2 = fma2(p0.y, w1, acc2);
                    acc2 = fma2(p1.x, w2, acc2); acc2 = fma2(p1.y, w3, acc2);
                }
                {
                    ulonglong2 p0 = *(const ulonglong2*)(pb + 192);
                    ulonglong2 p1 = *(const ulonglong2*)(pb + 194);
                    acc3 = fma2(p0.x, w0, acc3); acc3 = fma2(p0.y, w1, acc3);
                    acc3 = fma2(p1.x, w2, acc3); acc3 = fma2(p1.y, w3, acc3);
                }
            }
            // combine r-halves with lane partner (bh^1)
            u64 f0 = add2(acc0, shflx1(acc0));
            u64 f1 = add2(acc1, shflx1(acc1));
            u64 f2 = add2(acc2, shflx1(acc2));
            u64 f3 = add2(acc3, shflx1(acc3));

            // epilogue: this thread handles bp = bh*2, bh*2+1
            u64 full[4] = {f0, f1, f2, f3};
            float wxs[4] = {wx0, wx1, wx2, wx3};
            #pragma unroll
            for (int q = 0; q < 2; q++) {
                const int bp = bh * 2 + q;
                float uh0, uh1, ho0, ho1;
                unpack2(full[bp], uh0, uh1);
                unpack2(h2[bp * HT + jp], ho0, ho1);

                float pre0 = uh0 + wxs[2 * q];
                float pre1 = uh1 + wxs[2 * q + 1];

                float z0 = sigmoidf_(pre0 + bgv);
                float z1 = sigmoidf_(pre1 + bgv);

                float y0 = pre0 + buv, y1 = pre1 + buv;
                float e0 = __expf(-2.0f * fabsf(y0));
                float e1 = __expf(-2.0f * fabsf(y1));
                float c0 = copysignf(__fdividef(1.0f - e0, 1.0f + e0), y0);
                float c1 = copysignf(__fdividef(1.0f - e1, 1.0f + e1), y1);

                float hn0 = fmaf(fmaf(zs, 1.0f - z0, ns), c0, z0 * ho0);
                float hn1 = fmaf(fmaf(zs, 1.0f - z1, ns), c1, z1 * ho1);

                h2[bp * HT + jp] = pack2(hn0, hn1);
                size_t ob = ((size_t)t * Bb + b0 + 2 * bp) * Hh + hgb + jp;
                out[ob]      = hn0;
                out[ob + Hh] = hn1;
            }
        }
        __syncthreads();                                   // bar 3 (h2 for next A)
    }
}

// ======================================================================
// Launch
// ======================================================================
extern "C" void kernel_launch(void* const* d_in, const int* in_sizes, int n_in,
                              void* d_out, int out_size)
{
    const float* x    = (const float*)d_in[0];
    const float* h0   = (const float*)d_in[1];
    const float* W1   = (const float*)d_in[2];
    const float* W2   = (const float*)d_in[3];
    const float* U1   = (const float*)d_in[4];
    const float* U2   = (const float*)d_in[5];
    const float* bg   = (const float*)d_in[6];
    const float* bu   = (const float*)d_in[7];
    const float* zeta = (const float*)d_in[8];
    const float* nu   = (const float*)d_in[9];
    float* out = (float*)d_out;

    // 1) xw1 = x @ W1^T
    xw1_kernel<<<(Tt * Bb) / 64, 256>>>(x, W1);

    // 2) wx2 = xw1 @ W2^T
    const int wx2_smem = 2 * 64 * PM * sizeof(float);
    cudaFuncSetAttribute(wx2_kernel, cudaFuncAttributeMaxDynamicSharedMemorySize,
                         wx2_smem);
    dim3 g2((Tt * Bb) / 128, Hh / 128);
    wx2_kernel<<<g2, 256, wx2_smem>>>(W2);

    // 3) persistent cluster scan: 32 clusters x 8 CTAs = 256 CTAs, occ 2
    cudaFuncSetAttribute(scan_kernel, cudaFuncAttributeMaxDynamicSharedMemorySize,
                         SMEM_BYTES);
    scan_kernel<<<(Bb / BT) * NH, 256, SMEM_BYTES>>>(h0, U1, U2, bg, bu,
                                                     zeta, nu, out);
}